// round 2
// baseline (speedup 1.0000x reference)
#include <cuda_runtime.h>

// Problem constants
#define N_IMG 8
#define C_IN  64
#define HW    256
#define OC2   3

// Intermediate activation h (post conv1+bias+PReLU+fake-quant), exact fp32.
// 8*64*256*256 floats = 128 MiB device-global scratch (alloc-free workaround).
__device__ float g_h[N_IMG * C_IN * HW * HW];

// ---------------------------------------------------------------------------
// Packed f32x2 helpers (sm_100+). ptxas never auto-fuses these from C++.
// ---------------------------------------------------------------------------
__device__ __forceinline__ unsigned long long ffma2(unsigned long long a,
                                                    unsigned long long b,
                                                    unsigned long long c) {
    unsigned long long d;
    asm("fma.rn.f32x2 %0, %1, %2, %3;" : "=l"(d) : "l"(a), "l"(b), "l"(c));
    return d;
}
__device__ __forceinline__ unsigned long long pack2(float lo, float hi) {
    unsigned long long d;
    asm("mov.b64 %0, {%1, %2};" : "=l"(d) : "f"(lo), "f"(hi));
    return d;
}
__device__ __forceinline__ float2 unpack2(unsigned long long v) {
    float2 r;
    asm("mov.b64 {%0, %1}, %2;" : "=f"(r.x), "=f"(r.y) : "l"(v));
    return r;
}

// PReLU + 7-bit symmetric fake-quant (matches jnp: round half-to-even, clip [-64,63])
__device__ __forceinline__ float fq_act(float v, float a, float s) {
    v = (v >= 0.f) ? v : a * v;
    float q = rintf(v / s);
    q = fminf(fmaxf(q, -64.f), 63.f);
    return q * s;
}

// ---------------------------------------------------------------------------
// conv1: 64 -> 64, 3x3, pad 1, weight fake-quant, + bias + PReLU + act quant.
// One block per (n, output row h): 64 OC x 256 px.
// 256 threads: tid>>6 -> OC group of 16 (8 f32x2 pairs), tid&63 -> 4 px.
// ---------------------------------------------------------------------------
__global__ __launch_bounds__(256, 2)
void conv1_kernel(const float* __restrict__ x,  const float* __restrict__ w1,
                  const float* __restrict__ b1, const float* __restrict__ alpha1,
                  const float* __restrict__ sw1, const float* __restrict__ sa1)
{
    __shared__ __align__(16) float sIn[8][3][264];   // 8 cin x 3 rows x (w=-1..256, padded)
    __shared__ __align__(16) float sW[8][9][64];     // [cin][k][oc] -> oc-pairs are LDS.64

    const int h   = blockIdx.x;
    const int n   = blockIdx.y;
    const int tid = threadIdx.x;
    const int ocg = tid >> 6;          // 0..3
    const int pg  = tid & 63;          // 0..63
    const int p0  = pg << 2;           // 4 px per thread
    const int oc0 = ocg << 4;          // 16 oc per thread

    unsigned long long acc[8][4];
#pragma unroll
    for (int i = 0; i < 8; i++)
#pragma unroll
        for (int j = 0; j < 4; j++) acc[i][j] = 0ull;

    for (int c0 = 0; c0 < 64; c0 += 8) {
        if (c0) __syncthreads();
        // --- stage input tile (rows h-1..h+1, w=-1..256, zero padded) ---
        for (int i = tid; i < 8 * 3 * 264; i += 256) {
            int c = i / (3 * 264);
            int rem = i - c * (3 * 264);
            int r = rem / 264;
            int j = rem - r * 264;
            int w = j - 1, hh = h - 1 + r;
            float v = 0.f;
            if (j < 258 && (unsigned)w < 256u && (unsigned)hh < 256u)
                v = x[(((n << 6) + c0 + c) << 16) + (hh << 8) + w];
            sIn[c][r][j] = v;
        }
        // --- stage + fake-quant weights: wq = clip(rint(w/sw),-64,63)*sw ---
        for (int i = tid; i < 8 * 9 * 64; i += 256) {
            int c = i / 576;
            int rem = i - c * 576;
            int k = rem >> 6;
            int oc = rem & 63;
            float s = sw1[oc];
            float wv = w1[((oc << 6) + c0 + c) * 9 + k];
            float q = rintf(wv / s);
            q = fminf(fmaxf(q, -64.f), 63.f);
            sW[c][k][oc] = q * s;
        }
        __syncthreads();

#pragma unroll 2
        for (int c = 0; c < 8; c++) {
#pragma unroll
            for (int kh = 0; kh < 3; kh++) {
                const float* row = &sIn[c][kh][p0];
                float4 a4 = *(const float4*)row;          // 16B aligned (p0 % 4 == 0)
                float2 b2v = *(const float2*)(row + 4);
                unsigned long long xp[6];
                xp[0] = pack2(a4.x, a4.x);  xp[1] = pack2(a4.y, a4.y);
                xp[2] = pack2(a4.z, a4.z);  xp[3] = pack2(a4.w, a4.w);
                xp[4] = pack2(b2v.x, b2v.x); xp[5] = pack2(b2v.y, b2v.y);
#pragma unroll
                for (int kw = 0; kw < 3; kw++) {
                    const unsigned long long* wrow =
                        (const unsigned long long*)&sW[c][kh * 3 + kw][oc0];
#pragma unroll
                    for (int op = 0; op < 8; op++) {
                        unsigned long long wp = wrow[op];   // broadcast LDS.64, oc pair
#pragma unroll
                        for (int px = 0; px < 4; px++)
                            acc[op][px] = ffma2(wp, xp[kw + px], acc[op][px]);
                    }
                }
            }
        }
    }

    // --- epilogue: bias + PReLU + act fake-quant, coalesced float4 stores ---
#pragma unroll
    for (int op = 0; op < 8; op++) {
        float2 v0 = unpack2(acc[op][0]);
        float2 v1 = unpack2(acc[op][1]);
        float2 v2 = unpack2(acc[op][2]);
        float2 v3 = unpack2(acc[op][3]);
        int oce = oc0 + 2 * op;
        {
            float b = b1[oce], a = alpha1[oce], s = sa1[oce];
            float4 o;
            o.x = fq_act(v0.x + b, a, s); o.y = fq_act(v1.x + b, a, s);
            o.z = fq_act(v2.x + b, a, s); o.w = fq_act(v3.x + b, a, s);
            *(float4*)&g_h[(((n << 6) + oce) << 16) + (h << 8) + p0] = o;
        }
        int oco = oce + 1;
        {
            float b = b1[oco], a = alpha1[oco], s = sa1[oco];
            float4 o;
            o.x = fq_act(v0.y + b, a, s); o.y = fq_act(v1.y + b, a, s);
            o.z = fq_act(v2.y + b, a, s); o.w = fq_act(v3.y + b, a, s);
            *(float4*)&g_h[(((n << 6) + oco) << 16) + (h << 8) + p0] = o;
        }
    }
}

// ---------------------------------------------------------------------------
// conv2: 64 -> 3, 3x3, pad 1, same epilogue. ~5% of FLOPs; plain FFMA.
// One block per (n, 4 output rows). 256 threads: tid>>6 -> row, tid&63 -> 4 px.
// ---------------------------------------------------------------------------
__global__ __launch_bounds__(256)
void conv2_kernel(const float* __restrict__ w2, const float* __restrict__ b2,
                  const float* __restrict__ alpha2, const float* __restrict__ sw2,
                  const float* __restrict__ sa2, float* __restrict__ out)
{
    __shared__ __align__(16) float sIn[4][6][264];   // 4 cin x 6 rows (hb-1..hb+4)
    __shared__ float sW[4][9][3];

    const int h4 = blockIdx.x;
    const int n  = blockIdx.y;
    const int hb = h4 << 2;
    const int tid = threadIdx.x;
    const int r  = tid >> 6;           // 0..3 output row within block
    const int pg = tid & 63;
    const int p0 = pg << 2;

    float acc[3][4];
#pragma unroll
    for (int o = 0; o < 3; o++)
#pragma unroll
        for (int px = 0; px < 4; px++) acc[o][px] = 0.f;

    for (int c0 = 0; c0 < 64; c0 += 4) {
        if (c0) __syncthreads();
        for (int i = tid; i < 4 * 6 * 264; i += 256) {
            int c = i / (6 * 264);
            int rem = i - c * (6 * 264);
            int rr = rem / 264;
            int j = rem - rr * 264;
            int w = j - 1, hh = hb - 1 + rr;
            float v = 0.f;
            if (j < 258 && (unsigned)w < 256u && (unsigned)hh < 256u)
                v = g_h[(((n << 6) + c0 + c) << 16) + (hh << 8) + w];
            sIn[c][rr][j] = v;
        }
        if (tid < 4 * 9 * 3) {
            int c = tid / 27;
            int rem = tid - c * 27;
            int k = rem / 3;
            int oc = rem - k * 3;
            float s = sw2[oc];
            float wv = w2[((oc << 6) + c0 + c) * 9 + k];
            float q = rintf(wv / s);
            q = fminf(fmaxf(q, -64.f), 63.f);
            sW[c][k][oc] = q * s;
        }
        __syncthreads();

#pragma unroll
        for (int c = 0; c < 4; c++) {
#pragma unroll
            for (int kh = 0; kh < 3; kh++) {
                const float* row = &sIn[c][r + kh][p0];
                float4 a4 = *(const float4*)row;
                float2 bb = *(const float2*)(row + 4);
                float xv[6] = {a4.x, a4.y, a4.z, a4.w, bb.x, bb.y};
#pragma unroll
                for (int kw = 0; kw < 3; kw++) {
                    float w0 = sW[c][kh * 3 + kw][0];
                    float w1v = sW[c][kh * 3 + kw][1];
                    float w2v = sW[c][kh * 3 + kw][2];
#pragma unroll
                    for (int px = 0; px < 4; px++) {
                        float xvv = xv[kw + px];
                        acc[0][px] = fmaf(w0,  xvv, acc[0][px]);
                        acc[1][px] = fmaf(w1v, xvv, acc[1][px]);
                        acc[2][px] = fmaf(w2v, xvv, acc[2][px]);
                    }
                }
            }
        }
    }

#pragma unroll
    for (int o = 0; o < 3; o++) {
        float b = b2[o], a = alpha2[o], s = sa2[o];
        float4 ov;
        ov.x = fq_act(acc[o][0] + b, a, s);
        ov.y = fq_act(acc[o][1] + b, a, s);
        ov.z = fq_act(acc[o][2] + b, a, s);
        ov.w = fq_act(acc[o][3] + b, a, s);
        *(float4*)&out[((n * 3 + o) << 16) + ((hb + r) << 8) + p0] = ov;
    }
}

// ---------------------------------------------------------------------------
// Launch. Input order per metadata: x, w1, b1, w2, b2, alpha1, alpha2,
//                                   sw1, sw2, sa1, sa2. Output fp32 (8,3,256,256).
// ---------------------------------------------------------------------------
extern "C" void kernel_launch(void* const* d_in, const int* in_sizes, int n_in,
                              void* d_out, int out_size)
{
    (void)in_sizes; (void)n_in; (void)out_size;
    const float* x      = (const float*)d_in[0];
    const float* w1     = (const float*)d_in[1];
    const float* b1     = (const float*)d_in[2];
    const float* w2     = (const float*)d_in[3];
    const float* b2     = (const float*)d_in[4];
    const float* alpha1 = (const float*)d_in[5];
    const float* alpha2 = (const float*)d_in[6];
    const float* sw1    = (const float*)d_in[7];
    const float* sw2    = (const float*)d_in[8];
    const float* sa1    = (const float*)d_in[9];
    const float* sa2    = (const float*)d_in[10];

    conv1_kernel<<<dim3(HW, N_IMG), 256>>>(x, w1, b1, alpha1, sw1, sa1);
    conv2_kernel<<<dim3(HW / 4, N_IMG), 256>>>(w2, b2, alpha2, sw2, sa2, (float*)d_out);
}

// round 6
// speedup vs baseline: 1.3064x; 1.3064x over previous
#include <cuda_runtime.h>
#include <cuda_bf16.h>
#include <cstdint>

#define N_IMG 8
#define HW    256

// Intermediate h (post conv1 epilogue), fp32 NCHW, 128 MiB scratch.
__device__ float g_h[N_IMG * 64 * HW * HW];
// Pre-quantized integer conv1 weights as bf16: gB[((ck*9+tap)*64+oc)*16 + c%16]
__device__ __align__(16) __nv_bfloat16 gB[4 * 9 * 64 * 16];
// conv1 epilogue consts: [0,64)=b1, [64,128)=sw1
__device__ __align__(16) float g_c1const[128];

// ---------------- helpers ----------------
__device__ __forceinline__ uint32_t smem_u32(const void* p) {
    uint32_t a;
    asm("{ .reg .u64 t; cvta.to.shared.u64 t, %1; cvt.u32.u64 %0, t; }" : "=r"(a) : "l"(p));
    return a;
}
__device__ __forceinline__ unsigned long long ffma2(unsigned long long a,
                                                    unsigned long long b,
                                                    unsigned long long c) {
    unsigned long long d;
    asm("fma.rn.f32x2 %0, %1, %2, %3;" : "=l"(d) : "l"(a), "l"(b), "l"(c));
    return d;
}
__device__ __forceinline__ unsigned long long pack2(float lo, float hi) {
    unsigned long long d;
    asm("mov.b64 %0, {%1, %2};" : "=l"(d) : "f"(lo), "f"(hi));
    return d;
}
__device__ __forceinline__ float2 unpack2(unsigned long long v) {
    float2 r;
    asm("mov.b64 {%0, %1}, %2;" : "=f"(r.x), "=f"(r.y) : "l"(v));
    return r;
}
// D = A*B + C (in-place accumulate)
__device__ __forceinline__ void mma16816(float* c, uint32_t a0, uint32_t a1,
                                         uint32_t a2, uint32_t a3,
                                         uint32_t b0, uint32_t b1) {
    asm volatile(
        "mma.sync.aligned.m16n8k16.row.col.f32.bf16.bf16.f32 "
        "{%0,%1,%2,%3}, {%4,%5,%6,%7}, {%8,%9}, {%0,%1,%2,%3};"
        : "+f"(c[0]), "+f"(c[1]), "+f"(c[2]), "+f"(c[3])
        : "r"(a0), "r"(a1), "r"(a2), "r"(a3), "r"(b0), "r"(b1));
}
// D = A*B (C = 0) -- starts a fresh TC accumulation chain
__device__ __forceinline__ void mma16816_z(float* c, uint32_t a0, uint32_t a1,
                                           uint32_t a2, uint32_t a3,
                                           uint32_t b0, uint32_t b1) {
    asm volatile(
        "mma.sync.aligned.m16n8k16.row.col.f32.bf16.bf16.f32 "
        "{%0,%1,%2,%3}, {%4,%5,%6,%7}, {%8,%9}, {%10,%11,%12,%13};"
        : "=f"(c[0]), "=f"(c[1]), "=f"(c[2]), "=f"(c[3])
        : "r"(a0), "r"(a1), "r"(a2), "r"(a3), "r"(b0), "r"(b1),
          "f"(0.f), "f"(0.f), "f"(0.f), "f"(0.f));
}
__device__ __forceinline__ void ldmatrix4(uint32_t& r0, uint32_t& r1,
                                          uint32_t& r2, uint32_t& r3, uint32_t addr) {
    asm volatile("ldmatrix.sync.aligned.m8n8.x4.shared.b16 {%0,%1,%2,%3}, [%4];"
                 : "=r"(r0), "=r"(r1), "=r"(r2), "=r"(r3) : "r"(addr));
}
__device__ __forceinline__ float fq_act(float v, float a, float s) {
    v = (v >= 0.f) ? v : a * v;
    float q = rintf(v / s);
    q = fminf(fmaxf(q, -64.f), 63.f);
    return q * s;
}

// ---------------- prekernels ----------------
__global__ void quantw_kernel(const float* __restrict__ w1, const float* __restrict__ sw1) {
    int i = blockIdx.x * 256 + threadIdx.x;          // flat over w1: (oc*64 + c)*9 + tap
    if (i >= 64 * 64 * 9) return;
    int tap = i % 9;
    int t   = i / 9;
    int c   = t & 63;
    int oc  = t >> 6;
    float s = sw1[oc];
    float q = rintf(w1[i] / s);
    q = fminf(fmaxf(q, -64.f), 63.f);
    int ck = c >> 4;
    gB[((ck * 9 + tap) * 64 + oc) * 16 + (c & 15)] = __float2bfloat16(q);
}
__global__ void packc_kernel(const float* __restrict__ b1, const float* __restrict__ sw1) {
    int i = threadIdx.x;
    if (i < 64) g_c1const[i] = b1[i];
    else        g_c1const[i] = sw1[i - 64];
}

// ---------------- conv1: mma.sync implicit GEMM, short TC chains ----------------
// SMEM (dynamic, 95488 B):
//   A at 1024:  [term3][kh3][px1 264][c16] bf16, plane 8448B, 16B halves XOR-swizzled
//   B at 77056: [tap9][oc64][c16] bf16 (2048B per tap)
//   epilogue transpose reuses the A region.
#define A_OFF   1024
#define A_PLANE 8448
#define A_TERM  (3 * A_PLANE)
#define B_OFF   (A_OFF + 9 * A_PLANE)      // 77056
#define C1_SMEM (B_OFF + 9 * 2048)         // 95488

__global__ __launch_bounds__(256, 1)
void conv1_mma_kernel(const float* __restrict__ x,  const float* __restrict__ cst,
                      const float* __restrict__ alpha1, const float* __restrict__ sa1)
{
    extern __shared__ __align__(16) char smem[];
    const uint32_t sb = smem_u32(smem);
    const int h    = blockIdx.x;
    const int n    = blockIdx.y;
    const int tid  = threadIdx.x;
    const int wid  = tid >> 5;
    const int lane = tid & 31;

    // master accumulators (IEEE fp32 summation across chunks/terms)
    float master[2][8][4];
#pragma unroll
    for (int mt = 0; mt < 2; mt++)
#pragma unroll
        for (int nt = 0; nt < 8; nt++)
#pragma unroll
            for (int k = 0; k < 4; k++) master[mt][nt][k] = 0.f;

    const int rowIdx = lane & 15;
    const int khalf  = lane >> 4;
    const int bRow   = ((lane >> 2) << 5) + ((lane & 3) << 2);

    for (int ck = 0; ck < 4; ck++) {
        if (ck) __syncthreads();
        // ---- stage B chunk (18432 B straight copy) ----
        {
            const uint4* src = (const uint4*)(gB + ck * 9216);
            uint4* dst = (uint4*)(smem + B_OFF);
            for (int i = tid; i < 1152; i += 256) dst[i] = src[i];
        }
        // ---- stage A chunk: fp32 -> 3 bf16 terms ----
        for (int i = tid; i < 1584; i += 256) {       // (r3, kb2, px1 264)
            int r   = i / 528;
            int rem = i - r * 528;
            int kb  = rem / 264;
            int px1 = rem - kb * 264;
            int row = h - 1 + r;
            int px  = px1 - 1;
            bool valid = (px1 >= 1) && (px1 <= 256) && ((unsigned)row < 256u);
            const float* xp = x + (((n << 6) + (ck << 4) + (kb << 3)) << 16) + (row << 8) + px;
            unsigned short s0[8], s1[8], s2[8];
#pragma unroll
            for (int j = 0; j < 8; j++) {
                float v = valid ? __ldg(xp + (j << 16)) : 0.f;
                __nv_bfloat16 t0 = __float2bfloat16(v);
                float r1 = v - __bfloat162float(t0);
                __nv_bfloat16 t1 = __float2bfloat16(r1);
                float r2 = r1 - __bfloat162float(t1);
                __nv_bfloat16 t2 = __float2bfloat16(r2);
                s0[j] = __bfloat16_as_ushort(t0);
                s1[j] = __bfloat16_as_ushort(t1);
                s2[j] = __bfloat16_as_ushort(t2);
            }
            char* ab = smem + A_OFF + r * A_PLANE + px1 * 32
                     + ((kb ^ ((px1 >> 2) & 1)) << 4);
            *(uint4*)(ab)              = *(uint4*)s0;
            *(uint4*)(ab + A_TERM)     = *(uint4*)s1;
            *(uint4*)(ab + 2 * A_TERM) = *(uint4*)s2;
        }
        __syncthreads();

        // ---- compute: per term, fresh 9-tap TC chain, then IEEE add to master ----
#pragma unroll
        for (int term = 0; term < 3; term++) {
            float work[2][8][4];
#pragma unroll
            for (int kh = 0; kh < 3; kh++) {
#pragma unroll
                for (int kw = 0; kw < 3; kw++) {
                    const char* bt = smem + B_OFF + (kh * 3 + kw) * 2048 + bRow;
                    uint32_t bf[8][2];
#pragma unroll
                    for (int nt = 0; nt < 8; nt++) {
                        bf[nt][0] = *(const uint32_t*)(bt + nt * 256);
                        bf[nt][1] = *(const uint32_t*)(bt + nt * 256 + 16);
                    }
                    const uint32_t abase = sb + A_OFF + term * A_TERM + kh * A_PLANE;
#pragma unroll
                    for (int mt = 0; mt < 2; mt++) {
                        int px1 = (wid << 5) + (mt << 4) + kw + rowIdx;
                        uint32_t addr = abase + px1 * 32
                                      + ((khalf ^ ((px1 >> 2) & 1)) << 4);
                        uint32_t a0, a1, a2, a3;
                        ldmatrix4(a0, a1, a2, a3, addr);
                        if (kh == 0 && kw == 0) {
#pragma unroll
                            for (int nt = 0; nt < 8; nt++)
                                mma16816_z(work[mt][nt], a0, a1, a2, a3,
                                           bf[nt][0], bf[nt][1]);
                        } else {
#pragma unroll
                            for (int nt = 0; nt < 8; nt++)
                                mma16816(work[mt][nt], a0, a1, a2, a3,
                                         bf[nt][0], bf[nt][1]);
                        }
                    }
                }
            }
#pragma unroll
            for (int mt = 0; mt < 2; mt++)
#pragma unroll
                for (int nt = 0; nt < 8; nt++)
#pragma unroll
                    for (int k = 0; k < 4; k++)
                        master[mt][nt][k] += work[mt][nt][k];
        }
    }

    __syncthreads();
    // ---- epilogue: transpose through smem, then sw*D + b -> PReLU -> fq -> g_h ----
#pragma unroll
    for (int mt = 0; mt < 2; mt++) {
        int px = (wid << 5) + (mt << 4) + (lane >> 2);
#pragma unroll
        for (int nt = 0; nt < 8; nt++) {
            int col = (nt << 3) + ((lane & 3) << 1);
            *(float2*)(smem + A_OFF + px * 264 + col * 4) =
                make_float2(master[mt][nt][0], master[mt][nt][1]);
            *(float2*)(smem + A_OFF + (px + 8) * 264 + col * 4) =
                make_float2(master[mt][nt][2], master[mt][nt][3]);
        }
    }
    __syncthreads();
    {
        const char* ep = smem + A_OFF + tid * 264;
        float* dst = g_h + ((n << 6) << 16) + (h << 8) + tid;
#pragma unroll 8
        for (int oc = 0; oc < 64; oc++) {
            float v = *(const float*)(ep + oc * 4);
            float y = fmaf(v, __ldg(cst + 64 + oc), __ldg(cst + oc));
            dst[oc << 16] = fq_act(y, __ldg(alpha1 + oc), __ldg(sa1 + oc));
        }
    }
}

// ---------------- conv2: 64 -> 3, f32x2 + cheap staging ----------------
__global__ __launch_bounds__(256)
void conv2_kernel(const float* __restrict__ w2, const float* __restrict__ b2,
                  const float* __restrict__ alpha2, const float* __restrict__ sw2,
                  const float* __restrict__ sa2, float* __restrict__ out)
{
    __shared__ __align__(16) float sIn[4][6][264];
    __shared__ __align__(8) float2 sW2[4][9][3];

    const int hb  = blockIdx.x << 2;
    const int n   = blockIdx.y;
    const int tid = threadIdx.x;
    const int r   = tid >> 6;
    const int p0  = (tid & 63) << 2;

    unsigned long long acc2[3][2];
#pragma unroll
    for (int o = 0; o < 3; o++) { acc2[o][0] = 0ull; acc2[o][1] = 0ull; }

    for (int c0 = 0; c0 < 64; c0 += 4) {
        if (c0) __syncthreads();
#pragma unroll
        for (int c = 0; c < 4; c++)
#pragma unroll
            for (int rr = 0; rr < 6; rr++) {
                int hh = hb - 1 + rr;
                bool hok = (unsigned)hh < 256u;
                const float* ptr = g_h + (((n << 6) + c0 + c) << 16) + (hh << 8);
                sIn[c][rr][tid] = (hok && tid >= 1) ? ptr[tid - 1] : 0.f;
                if (tid < 8)
                    sIn[c][rr][tid + 256] = (hok && tid == 0) ? ptr[255] : 0.f;
            }
        if (tid < 108) {
            int c = tid / 27;
            int rem = tid - c * 27;
            int k = rem / 3;
            int o = rem - k * 3;
            float s = sw2[o];
            float q = rintf(w2[((o << 6) + c0 + c) * 9 + k] / s);
            q = fminf(fmaxf(q, -64.f), 63.f);
            float qs = q * s;
            sW2[c][k][o] = make_float2(qs, qs);
        }
        __syncthreads();

#pragma unroll
        for (int c = 0; c < 4; c++)
#pragma unroll
            for (int kh = 0; kh < 3; kh++) {
                const float* row = &sIn[c][r + kh][p0];
                float4 a4 = *(const float4*)row;
                float2 bb = *(const float2*)(row + 4);
                unsigned long long p[5];
                p[0] = pack2(a4.x, a4.y); p[1] = pack2(a4.y, a4.z);
                p[2] = pack2(a4.z, a4.w); p[3] = pack2(a4.w, bb.x);
                p[4] = pack2(bb.x, bb.y);
#pragma unroll
                for (int kw = 0; kw < 3; kw++)
#pragma unroll
                    for (int o = 0; o < 3; o++) {
                        unsigned long long ww =
                            *(const unsigned long long*)&sW2[c][kh * 3 + kw][o];
                        acc2[o][0] = ffma2(ww, p[kw],     acc2[o][0]);
                        acc2[o][1] = ffma2(ww, p[kw + 2], acc2[o][1]);
                    }
            }
    }

#pragma unroll
    for (int o = 0; o < 3; o++) {
        float b = b2[o], a = alpha2[o], s = sa2[o];
        float2 u0 = unpack2(acc2[o][0]);
        float2 u1 = unpack2(acc2[o][1]);
        float4 ov;
        ov.x = fq_act(u0.x + b, a, s);
        ov.y = fq_act(u0.y + b, a, s);
        ov.z = fq_act(u1.x + b, a, s);
        ov.w = fq_act(u1.y + b, a, s);
        *(float4*)&out[((n * 3 + o) << 16) + ((hb + r) << 8) + p0] = ov;
    }
}

// ---------------- launch ----------------
extern "C" void kernel_launch(void* const* d_in, const int* in_sizes, int n_in,
                              void* d_out, int out_size)
{
    (void)in_sizes; (void)n_in; (void)out_size;
    const float* x      = (const float*)d_in[0];
    const float* w1     = (const float*)d_in[1];
    const float* b1     = (const float*)d_in[2];
    const float* w2     = (const float*)d_in[3];
    const float* b2     = (const float*)d_in[4];
    const float* alpha1 = (const float*)d_in[5];
    const float* alpha2 = (const float*)d_in[6];
    const float* sw1    = (const float*)d_in[7];
    const float* sw2    = (const float*)d_in[8];
    const float* sa1    = (const float*)d_in[9];
    const float* sa2    = (const float*)d_in[10];

    static float* c1c = nullptr;
    if (!c1c) cudaGetSymbolAddress((void**)&c1c, g_c1const);

    cudaFuncSetAttribute(conv1_mma_kernel,
                         cudaFuncAttributeMaxDynamicSharedMemorySize, C1_SMEM);

    quantw_kernel<<<144, 256>>>(w1, sw1);
    packc_kernel<<<1, 128>>>(b1, sw1);
    conv1_mma_kernel<<<dim3(HW, N_IMG), 256, C1_SMEM>>>(x, c1c, alpha1, sa1);
    conv2_kernel<<<dim3(HW / 4, N_IMG), 256>>>(w2, b2, alpha2, sw2, sa2, (float*)d_out);
}